// round 14
// baseline (speedup 1.0000x reference)
#include <cuda_runtime.h>
#include <cstdint>

#define EPSC   1e-6f
#define L2E    1.4426950408889634f
#define L2E2C  2.0813689810056077f
#define LN2F   0.6931471805599453f
#define SQRT2  1.41421356237309515f
#define TPB    128
#define NWARP  4
#define TILE   128
#define ASTRIDE 20
#define MAXPART 4096

__device__ double       g_part[MAXPART];
__device__ unsigned int g_count = 0;

typedef unsigned long long ull;

__device__ __forceinline__ float ex2_approx(float x) {
    float y; asm("ex2.approx.ftz.f32 %0, %1;" : "=f"(y) : "f"(x)); return y;
}
__device__ __forceinline__ float lg2_approx(float x) {
    float y; asm("lg2.approx.ftz.f32 %0, %1;" : "=f"(y) : "f"(x)); return y;
}
__device__ __forceinline__ float sqrt_approx(float x) {
    float y; asm("sqrt.approx.ftz.f32 %0, %1;" : "=f"(y) : "f"(x)); return y;
}
__device__ __forceinline__ uint32_t to_tf32(float v) {
    uint32_t r; asm("cvt.rna.tf32.f32 %0, %1;" : "=r"(r) : "f"(v)); return r;
}
__device__ __forceinline__ void mma_tf32(float& d0, float& d1, float& d2, float& d3,
                                         uint32_t a0, uint32_t a1, uint32_t a2, uint32_t a3,
                                         uint32_t b0, uint32_t b1) {
    asm volatile(
        "mma.sync.aligned.m16n8k8.row.col.f32.tf32.tf32.f32 "
        "{%0,%1,%2,%3}, {%4,%5,%6,%7}, {%8,%9}, {%0,%1,%2,%3};"
        : "+f"(d0), "+f"(d1), "+f"(d2), "+f"(d3)
        : "r"(a0), "r"(a1), "r"(a2), "r"(a3), "r"(b0), "r"(b1));
}

// lgamma(1+x), x in [0,1): A&S 6.1.36 minimax for Gamma(1+x), |eps|<=3e-7.
__device__ __forceinline__ float lgamma1p(float x) {
    float p = 0.035868343f;
    p = fmaf(p, x, -0.193527818f);
    p = fmaf(p, x,  0.482199394f);
    p = fmaf(p, x, -0.756704078f);
    p = fmaf(p, x,  0.918206857f);
    p = fmaf(p, x, -0.897056937f);
    p = fmaf(p, x,  0.988205891f);
    p = fmaf(p, x, -0.577191652f);
    p = fmaf(p, x,  1.0f);
    return lg2_approx(p) * LN2F;
}

// Shared layout: hi/lo tf32 tiles, K padded to 16, row stride 20 words.
struct Smem {
    uint32_t Ahi[TILE * ASTRIDE];
    uint32_t Alo[TILE * ASTRIDE];
    uint32_t Bhi[TILE * ASTRIDE];
    uint32_t Blo[TILE * ASTRIDE];
    float    ej[TILE];
    float    ei[TILE];
    double   ws[NWARP];
    int      last;
};

__device__ __forceinline__ void stage_row(uint32_t* hi, uint32_t* lo, int row,
                                          const float* v10) {
    #pragma unroll
    for (int k = 0; k < 10; ++k) {
        uint32_t h = to_tf32(v10[k]);
        float hf = __uint_as_float(h);
        hi[row * ASTRIDE + k] = h;
        lo[row * ASTRIDE + k] = to_tf32(v10[k] - hf);
    }
}

__global__ void __launch_bounds__(TPB, 5) fused_kernel(
        const float* __restrict__ beta,  const float* __restrict__ gamma,
        const float* __restrict__ zi,    const float* __restrict__ zj,
        const float* __restrict__ vC,
        const int*   __restrict__ si,    const int*   __restrict__ sj,
        const int*   __restrict__ spi,   const int*   __restrict__ spj,
        float* __restrict__ out,
        int S_I, int S_J, int nnz, int gx, int nDense, int nTotal) {

    __shared__ Smem sm;
    const int bid = blockIdx.x;
    const int tid = threadIdx.x;
    const int lane = tid & 31, warp = tid >> 5;

    float dsum = 0.f;
    float lsum = 0.f;

    if (bid < nDense) {
        const int bx = bid % gx, by = bid / gx;

        // zero hi/lo tiles (covers K-pad cols 10..15 and invalid rows)
        {
            uint4 z4 = make_uint4(0u, 0u, 0u, 0u);
            uint4* p = (uint4*)sm.Ahi;   // 4 arrays contiguous: 4*2560 words
            for (int i = tid; i < (4 * TILE * ASTRIDE) / 4; i += TPB) p[i] = z4;
        }
        __syncthreads();

        // ---- stage: thread tid owns row tid of A (i side) and B (j side) ----
        {
            int ig = bx * TILE + tid;
            float ei = 0.f;
            if (ig < S_I) {
                int idx = __ldg(si + ig);
                float4 a0 = __ldg((const float4*)(zi + (size_t)idx * 8));
                float4 a1 = __ldg((const float4*)(zi + (size_t)idx * 8 + 4));
                float v[10];
                v[0]=a0.x+EPSC; v[1]=a0.y+EPSC; v[2]=a0.z+EPSC; v[3]=a0.w+EPSC;
                v[4]=a1.x+EPSC; v[5]=a1.y+EPSC; v[6]=a1.z+EPSC; v[7]=a1.w+EPSC;
                float n = 0.f;
                #pragma unroll
                for (int k = 0; k < 8; ++k) n = fmaf(v[k], v[k], n);
                const float SC = -SQRT2 * L2E2C;
                #pragma unroll
                for (int k = 0; k < 8; ++k) v[k] *= SC;
                v[8] = n * L2E2C;       // pairs with B's 1
                v[9] = L2E2C;           // pairs with B's |b|^2
                stage_row(sm.Ahi, sm.Alo, tid, v);
                ei = ex2_approx(__ldg(beta + idx) * L2E);
            }
            sm.ei[tid] = ei;
        }
        {
            int jg = by * TILE + tid;
            float ejv = 0.f;
            if (jg < S_J) {
                int idx = __ldg(sj + jg);
                float4 b0 = __ldg((const float4*)(zj + (size_t)idx * 8));
                float4 b1 = __ldg((const float4*)(zj + (size_t)idx * 8 + 4));
                float v[10];
                v[0]=b0.x*SQRT2; v[1]=b0.y*SQRT2; v[2]=b0.z*SQRT2; v[3]=b0.w*SQRT2;
                v[4]=b1.x*SQRT2; v[5]=b1.y*SQRT2; v[6]=b1.z*SQRT2; v[7]=b1.w*SQRT2;
                float n = 0.f;
                #pragma unroll
                for (int k = 0; k < 8; ++k) n = fmaf(b0.x, 0.f, n);  // placeholder (recomputed below)
                n = b0.x*b0.x + b0.y*b0.y + b0.z*b0.z + b0.w*b0.w
                  + b1.x*b1.x + b1.y*b1.y + b1.z*b1.z + b1.w*b1.w;
                v[8] = 1.0f;
                v[9] = n;
                stage_row(sm.Bhi, sm.Blo, tid, v);
                ejv = ex2_approx(__ldg(gamma + idx) * L2E);
            }
            sm.ej[tid] = ejv;
        }
        __syncthreads();

        // ---- MMA mainloop: warp owns rows [warp*32, warp*32+32) ----
        const int tig = lane & 3, gid = lane >> 2;
        #pragma unroll
        for (int g = 0; g < 2; ++g) {
            const int rbase = warp * 32 + g * 16;
            // A fragments (hi & lo), 2 k-steps
            uint32_t ah[2][4], al[2][4];
            #pragma unroll
            for (int ks = 0; ks < 2; ++ks) {
                int c = tig + ks * 8;
                int r0 = (rbase + gid) * ASTRIDE, r1 = (rbase + gid + 8) * ASTRIDE;
                ah[ks][0] = sm.Ahi[r0 + c];     ah[ks][1] = sm.Ahi[r1 + c];
                ah[ks][2] = sm.Ahi[r0 + c + 4]; ah[ks][3] = sm.Ahi[r1 + c + 4];
                al[ks][0] = sm.Alo[r0 + c];     al[ks][1] = sm.Alo[r1 + c];
                al[ks][2] = sm.Alo[r0 + c + 4]; al[ks][3] = sm.Alo[r1 + c + 4];
            }
            float ar0 = 0.f, ar1 = 0.f;
            #pragma unroll 1
            for (int n = 0; n < TILE; n += 8) {
                uint32_t bh[2][2], bl[2][2];
                #pragma unroll
                for (int ks = 0; ks < 2; ++ks) {
                    int c = tig + ks * 8;
                    int rn = (n + gid) * ASTRIDE;
                    bh[ks][0] = sm.Bhi[rn + c]; bh[ks][1] = sm.Bhi[rn + c + 4];
                    bl[ks][0] = sm.Blo[rn + c]; bl[ks][1] = sm.Blo[rn + c + 4];
                }
                float d0 = 0.f, d1 = 0.f, d2 = 0.f, d3 = 0.f;
                mma_tf32(d0,d1,d2,d3, ah[0][0],ah[0][1],ah[0][2],ah[0][3], bh[0][0],bh[0][1]);
                mma_tf32(d0,d1,d2,d3, ah[1][0],ah[1][1],ah[1][2],ah[1][3], bh[1][0],bh[1][1]);
                mma_tf32(d0,d1,d2,d3, ah[0][0],ah[0][1],ah[0][2],ah[0][3], bl[0][0],bl[0][1]);
                mma_tf32(d0,d1,d2,d3, ah[1][0],ah[1][1],ah[1][2],ah[1][3], bl[1][0],bl[1][1]);
                mma_tf32(d0,d1,d2,d3, al[0][0],al[0][1],al[0][2],al[0][3], bh[0][0],bh[0][1]);
                mma_tf32(d0,d1,d2,d3, al[1][0],al[1][1],al[1][2],al[1][3], bh[1][0],bh[1][1]);
                // D = (L2E*d)^2 at (row, col): c0/c1 row rbase+gid, c2/c3 +8
                float2 ej2 = *(const float2*)&sm.ej[n + 2 * tig];
                ar0 = fmaf(ex2_approx(-sqrt_approx(fmaxf(d0, 0.f))), ej2.x, ar0);
                ar0 = fmaf(ex2_approx(-sqrt_approx(fmaxf(d1, 0.f))), ej2.y, ar0);
                ar1 = fmaf(ex2_approx(-sqrt_approx(fmaxf(d2, 0.f))), ej2.x, ar1);
                ar1 = fmaf(ex2_approx(-sqrt_approx(fmaxf(d3, 0.f))), ej2.y, ar1);
            }
            dsum = fmaf(ar0, sm.ei[rbase + gid], dsum);
            dsum = fmaf(ar1, sm.ei[rbase + gid + 8], dsum);
        }
    }

    // ================= SPARSE link term: all blocks cooperate =================
    {
        int e = bid * TPB + tid;
        int stride = nTotal * TPB;
        #pragma unroll 2
        for (; e < nnz; e += stride) {
            int a = __ldg(spi + e), b = __ldg(spj + e);
            float4 a0 = __ldg((const float4*)(zi + (size_t)a * 8));
            float4 a1 = __ldg((const float4*)(zi + (size_t)a * 8 + 4));
            float4 b0 = __ldg((const float4*)(zj + (size_t)b * 8));
            float4 b1 = __ldg((const float4*)(zj + (size_t)b * 8 + 4));
            float d2 = 0.f, dx;
            dx = a0.x - b0.x + EPSC; d2 = fmaf(dx, dx, d2);
            dx = a0.y - b0.y + EPSC; d2 = fmaf(dx, dx, d2);
            dx = a0.z - b0.z + EPSC; d2 = fmaf(dx, dx, d2);
            dx = a0.w - b0.w + EPSC; d2 = fmaf(dx, dx, d2);
            dx = a1.x - b1.x + EPSC; d2 = fmaf(dx, dx, d2);
            dx = a1.y - b1.y + EPSC; d2 = fmaf(dx, dx, d2);
            dx = a1.z - b1.z + EPSC; d2 = fmaf(dx, dx, d2);
            dx = a1.w - b1.w + EPSC; d2 = fmaf(dx, dx, d2);
            float dist = sqrt_approx(d2);
            float v    = __ldg(vC + e);
            float bias = __ldg(beta + a) + __ldg(gamma + b);
            lsum += fmaf(v, bias - dist, -lgamma1p(v));
        }
    }

    // ---- deterministic block reduction: (link - dense) in double ----
    double t = (double)lsum - (double)dsum;
    #pragma unroll
    for (int o = 16; o; o >>= 1) t += __shfl_down_sync(0xFFFFFFFFu, t, o);
    if (lane == 0) sm.ws[warp] = t;
    __syncthreads();
    if (tid == 0) {
        double b = 0.0;
        #pragma unroll
        for (int k = 0; k < NWARP; ++k) b += sm.ws[k];
        g_part[bid] = b;
        __threadfence();
        unsigned int done = atomicAdd(&g_count, 1u);
        sm.last = (done == (unsigned int)(nTotal - 1)) ? 1 : 0;
    }
    __syncthreads();

    if (sm.last) {
        __threadfence();
        double s = 0.0;
        for (int k = tid; k < nTotal; k += TPB) s += __ldcg(&g_part[k]);
        #pragma unroll
        for (int o = 16; o; o >>= 1) s += __shfl_down_sync(0xFFFFFFFFu, s, o);
        __syncthreads();
        if (lane == 0) sm.ws[warp] = s;
        __syncthreads();
        if (tid == 0) {
            double r = 0.0;
            #pragma unroll
            for (int k = 0; k < NWARP; ++k) r += sm.ws[k];
            out[0] = (float)r;
            g_count = 0;
        }
    }
}

extern "C" void kernel_launch(void* const* d_in, const int* in_sizes, int n_in,
                              void* d_out, int out_size) {
    const float* beta  = (const float*)d_in[0];
    const float* gamma = (const float*)d_in[1];
    const float* zi    = (const float*)d_in[2];
    const float* zj    = (const float*)d_in[3];
    const float* vC    = (const float*)d_in[4];
    const int*   si    = (const int*)d_in[5];
    const int*   sj    = (const int*)d_in[6];
    const int*   spi   = (const int*)d_in[7];
    const int*   spj   = (const int*)d_in[8];

    int S_I = in_sizes[5];
    int S_J = in_sizes[6];
    int NNZ = in_sizes[4];

    int gx = (S_I + TILE - 1) / TILE;   // 47 for 6000
    int gy = (S_J + TILE - 1) / TILE;   // 47 for 6000
    int nDense = gx * gy;               // 2209
    int nTotal = nDense;
    if (nTotal > MAXPART) nTotal = MAXPART;

    fused_kernel<<<nTotal, TPB>>>(beta, gamma, zi, zj, vC, si, sj, spi, spj,
                                  (float*)d_out, S_I, S_J, NNZ,
                                  gx, nDense, nTotal);
}

// round 15
// speedup vs baseline: 1.1572x; 1.1572x over previous
#include <cuda_runtime.h>
#include <cstdint>

#define EPSC   1e-6f
#define L2E    1.4426950408889634f
#define L2E2C  2.0813689810056077f
#define LN2F   0.6931471805599453f
#define SQRT2  1.41421356237309515f
#define TPB    128
#define NWARP  4
#define TILE   128
#define PADR   8192
#define MAXPART 4096

__device__ uint4  gAhi[PADR * 4];
__device__ uint4  gAlo[PADR * 4];
__device__ uint4  gBhi[PADR * 4];
__device__ uint4  gBlo[PADR * 4];
__device__ float  gEi[PADR];
__device__ float  gEj[PADR];
__device__ double g_part[MAXPART];
__device__ unsigned int g_count = 0;

__device__ __forceinline__ float ex2_approx(float x) {
    float y; asm("ex2.approx.ftz.f32 %0, %1;" : "=f"(y) : "f"(x)); return y;
}
__device__ __forceinline__ float lg2_approx(float x) {
    float y; asm("lg2.approx.ftz.f32 %0, %1;" : "=f"(y) : "f"(x)); return y;
}
__device__ __forceinline__ float sqrt_approx(float x) {
    float y; asm("sqrt.approx.ftz.f32 %0, %1;" : "=f"(y) : "f"(x)); return y;
}
__device__ __forceinline__ uint32_t to_tf32(float v) {
    uint32_t r; asm("cvt.rna.tf32.f32 %0, %1;" : "=r"(r) : "f"(v)); return r;
}
__device__ __forceinline__ void mma_tf32(float& d0, float& d1, float& d2, float& d3,
                                         uint32_t a0, uint32_t a1, uint32_t a2, uint32_t a3,
                                         uint32_t b0, uint32_t b1) {
    asm volatile(
        "mma.sync.aligned.m16n8k8.row.col.f32.tf32.tf32.f32 "
        "{%0,%1,%2,%3}, {%4,%5,%6,%7}, {%8,%9}, {%0,%1,%2,%3};"
        : "+f"(d0), "+f"(d1), "+f"(d2), "+f"(d3)
        : "r"(a0), "r"(a1), "r"(a2), "r"(a3), "r"(b0), "r"(b1));
}
__device__ __forceinline__ float lgamma1p(float x) {
    float p = 0.035868343f;
    p = fmaf(p, x, -0.193527818f);
    p = fmaf(p, x,  0.482199394f);
    p = fmaf(p, x, -0.756704078f);
    p = fmaf(p, x,  0.918206857f);
    p = fmaf(p, x, -0.897056937f);
    p = fmaf(p, x,  0.988205891f);
    p = fmaf(p, x, -0.577191652f);
    p = fmaf(p, x,  1.0f);
    return lg2_approx(p) * LN2F;
}

// permuted fragment-order store: word t*4+q of a row holds k-dim (t + 4q)
__device__ __forceinline__ void store16(uint4* hi, uint4* lo, int r, const float* v10) {
    float w[16];
    #pragma unroll
    for (int k = 0; k < 16; ++k) w[k] = (k < 10) ? v10[k] : 0.f;
    #pragma unroll
    for (int t = 0; t < 4; ++t) {
        uint4 h, l;
        h.x = to_tf32(w[t]);      l.x = to_tf32(w[t]      - __uint_as_float(h.x));
        h.y = to_tf32(w[t + 4]);  l.y = to_tf32(w[t + 4]  - __uint_as_float(h.y));
        h.z = to_tf32(w[t + 8]);  l.z = to_tf32(w[t + 8]  - __uint_as_float(h.z));
        h.w = to_tf32(w[t + 12]); l.w = to_tf32(w[t + 12] - __uint_as_float(h.w));
        hi[r * 4 + t] = h;
        lo[r * 4 + t] = l;
    }
}

__global__ void prep_kernel(const float* __restrict__ beta,
                            const float* __restrict__ gamma,
                            const float* __restrict__ zi,
                            const float* __restrict__ zj,
                            const int*   __restrict__ si,
                            const int*   __restrict__ sj,
                            int S_I, int S_J, int padI, int padJ) {
    int r = blockIdx.x * blockDim.x + threadIdx.x;
    if (r < padI) {
        float v[10] = {0.f, 0.f, 0.f, 0.f, 0.f, 0.f, 0.f, 0.f, 0.f, 0.f};
        float e = 0.f;
        if (r < S_I) {
            int idx = __ldg(si + r);
            float4 a0 = __ldg((const float4*)(zi + (size_t)idx * 8));
            float4 a1 = __ldg((const float4*)(zi + (size_t)idx * 8 + 4));
            float t[8] = {a0.x + EPSC, a0.y + EPSC, a0.z + EPSC, a0.w + EPSC,
                          a1.x + EPSC, a1.y + EPSC, a1.z + EPSC, a1.w + EPSC};
            float n = 0.f;
            #pragma unroll
            for (int k = 0; k < 8; ++k) n = fmaf(t[k], t[k], n);
            const float SC = -SQRT2 * L2E2C;
            #pragma unroll
            for (int k = 0; k < 8; ++k) v[k] = SC * t[k];
            v[8] = n * L2E2C;   // pairs with B's 1
            v[9] = L2E2C;       // pairs with B's |b|^2
            e = ex2_approx(__ldg(beta + idx) * L2E);
        }
        store16(gAhi, gAlo, r, v);
        gEi[r] = e;
    }
    if (r < padJ) {
        float v[10] = {0.f, 0.f, 0.f, 0.f, 0.f, 0.f, 0.f, 0.f, 0.f, 0.f};
        float e = 0.f;
        if (r < S_J) {
            int idx = __ldg(sj + r);
            float4 b0 = __ldg((const float4*)(zj + (size_t)idx * 8));
            float4 b1 = __ldg((const float4*)(zj + (size_t)idx * 8 + 4));
            float n = b0.x*b0.x + b0.y*b0.y + b0.z*b0.z + b0.w*b0.w
                    + b1.x*b1.x + b1.y*b1.y + b1.z*b1.z + b1.w*b1.w;
            v[0] = b0.x*SQRT2; v[1] = b0.y*SQRT2; v[2] = b0.z*SQRT2; v[3] = b0.w*SQRT2;
            v[4] = b1.x*SQRT2; v[5] = b1.y*SQRT2; v[6] = b1.z*SQRT2; v[7] = b1.w*SQRT2;
            v[8] = 1.0f;
            v[9] = n;
            e = ex2_approx(__ldg(gamma + idx) * L2E);
        }
        store16(gBhi, gBlo, r, v);
        gEj[r] = e;
    }
}

__global__ void __launch_bounds__(TPB, 6) fused_kernel(
        const float* __restrict__ beta,  const float* __restrict__ gamma,
        const float* __restrict__ zi,    const float* __restrict__ zj,
        const float* __restrict__ vC,
        const int*   __restrict__ spi,   const int*   __restrict__ spj,
        float* __restrict__ out,
        int nnz, int gx, int nDense, int nTotal) {

    __shared__ double ws[NWARP];
    __shared__ int    s_last;

    const int bid = blockIdx.x;
    const int tid = threadIdx.x;
    const int lane = tid & 31, warp = tid >> 5;

    float dsum = 0.f;
    float lsum = 0.f;

    if (bid < nDense) {
        const int bx = bid % gx, by = bid / gx;
        const int tig = lane & 3, gid = lane >> 2;

        #pragma unroll
        for (int g = 0; g < 2; ++g) {
            const int r0 = bx * TILE + warp * 32 + g * 16 + gid;
            const int r1 = r0 + 8;
            uint4 A0h = __ldg(&gAhi[r0 * 4 + tig]);
            uint4 A1h = __ldg(&gAhi[r1 * 4 + tig]);
            uint4 A0l = __ldg(&gAlo[r0 * 4 + tig]);
            uint4 A1l = __ldg(&gAlo[r1 * 4 + tig]);
            float ar0 = 0.f, ar1 = 0.f;
            #pragma unroll 1
            for (int n = 0; n < TILE; n += 8) {
                const int rn = by * TILE + n + gid;
                uint4 Bh = __ldg(&gBhi[rn * 4 + tig]);
                uint4 Bl = __ldg(&gBlo[rn * 4 + tig]);
                float d0 = 0.f, d1 = 0.f, d2 = 0.f, d3 = 0.f;
                mma_tf32(d0,d1,d2,d3, A0h.x,A1h.x,A0h.y,A1h.y, Bh.x,Bh.y); // ks0 hi*hi
                mma_tf32(d0,d1,d2,d3, A0h.z,A1h.z,A0h.w,A1h.w, Bh.z,Bh.w); // ks1 hi*hi
                mma_tf32(d0,d1,d2,d3, A0h.x,A1h.x,A0h.y,A1h.y, Bl.x,Bl.y); // ks0 hi*lo
                mma_tf32(d0,d1,d2,d3, A0h.z,A1h.z,A0h.w,A1h.w, Bl.z,Bl.w); // ks1 hi*lo
                mma_tf32(d0,d1,d2,d3, A0l.x,A1l.x,A0l.y,A1l.y, Bh.x,Bh.y); // ks0 lo*hi
                mma_tf32(d0,d1,d2,d3, A0l.z,A1l.z,A0l.w,A1l.w, Bh.z,Bh.w); // ks1 lo*hi
                float2 ej2 = __ldg((const float2*)&gEj[by * TILE + n + 2 * tig]);
                ar0 = fmaf(ex2_approx(-sqrt_approx(fmaxf(d0, 0.f))), ej2.x, ar0);
                ar0 = fmaf(ex2_approx(-sqrt_approx(fmaxf(d1, 0.f))), ej2.y, ar0);
                ar1 = fmaf(ex2_approx(-sqrt_approx(fmaxf(d2, 0.f))), ej2.x, ar1);
                ar1 = fmaf(ex2_approx(-sqrt_approx(fmaxf(d3, 0.f))), ej2.y, ar1);
            }
            dsum = fmaf(ar0, __ldg(&gEi[r0]), dsum);
            dsum = fmaf(ar1, __ldg(&gEi[r1]), dsum);
        }
    }

    // ================= SPARSE link term: all blocks cooperate =================
    {
        int e = bid * TPB + tid;
        int stride = nTotal * TPB;
        #pragma unroll 2
        for (; e < nnz; e += stride) {
            int a = __ldg(spi + e), b = __ldg(spj + e);
            float4 a0 = __ldg((const float4*)(zi + (size_t)a * 8));
            float4 a1 = __ldg((const float4*)(zi + (size_t)a * 8 + 4));
            float4 b0 = __ldg((const float4*)(zj + (size_t)b * 8));
            float4 b1 = __ldg((const float4*)(zj + (size_t)b * 8 + 4));
            float d2 = 0.f, dx;
            dx = a0.x - b0.x + EPSC; d2 = fmaf(dx, dx, d2);
            dx = a0.y - b0.y + EPSC; d2 = fmaf(dx, dx, d2);
            dx = a0.z - b0.z + EPSC; d2 = fmaf(dx, dx, d2);
            dx = a0.w - b0.w + EPSC; d2 = fmaf(dx, dx, d2);
            dx = a1.x - b1.x + EPSC; d2 = fmaf(dx, dx, d2);
            dx = a1.y - b1.y + EPSC; d2 = fmaf(dx, dx, d2);
            dx = a1.z - b1.z + EPSC; d2 = fmaf(dx, dx, d2);
            dx = a1.w - b1.w + EPSC; d2 = fmaf(dx, dx, d2);
            float dist = sqrt_approx(d2);
            float v    = __ldg(vC + e);
            float bias = __ldg(beta + a) + __ldg(gamma + b);
            lsum += fmaf(v, bias - dist, -lgamma1p(v));
        }
    }

    // ---- deterministic block reduction: (link - dense) in double ----
    double t = (double)lsum - (double)dsum;
    #pragma unroll
    for (int o = 16; o; o >>= 1) t += __shfl_down_sync(0xFFFFFFFFu, t, o);
    if (lane == 0) ws[warp] = t;
    __syncthreads();
    if (tid == 0) {
        double b = 0.0;
        #pragma unroll
        for (int k = 0; k < NWARP; ++k) b += ws[k];
        g_part[bid] = b;
        __threadfence();
        unsigned int done = atomicAdd(&g_count, 1u);
        s_last = (done == (unsigned int)(nTotal - 1)) ? 1 : 0;
    }
    __syncthreads();

    if (s_last) {
        __threadfence();
        double s = 0.0;
        for (int k = tid; k < nTotal; k += TPB) s += __ldcg(&g_part[k]);
        #pragma unroll
        for (int o = 16; o; o >>= 1) s += __shfl_down_sync(0xFFFFFFFFu, s, o);
        __syncthreads();
        if (lane == 0) ws[warp] = s;
        __syncthreads();
        if (tid == 0) {
            double r = 0.0;
            #pragma unroll
            for (int k = 0; k < NWARP; ++k) r += ws[k];
            out[0] = (float)r;
            g_count = 0;
        }
    }
}

extern "C" void kernel_launch(void* const* d_in, const int* in_sizes, int n_in,
                              void* d_out, int out_size) {
    const float* beta  = (const float*)d_in[0];
    const float* gamma = (const float*)d_in[1];
    const float* zi    = (const float*)d_in[2];
    const float* zj    = (const float*)d_in[3];
    const float* vC    = (const float*)d_in[4];
    const int*   si    = (const int*)d_in[5];
    const int*   sj    = (const int*)d_in[6];
    const int*   spi   = (const int*)d_in[7];
    const int*   spj   = (const int*)d_in[8];

    int S_I = in_sizes[5];
    int S_J = in_sizes[6];
    int NNZ = in_sizes[4];

    int gx = (S_I + TILE - 1) / TILE;   // 47 for 6000
    int gy = (S_J + TILE - 1) / TILE;   // 47 for 6000
    int padI = gx * TILE;
    int padJ = gy * TILE;
    if (padI > PADR) padI = PADR;
    if (padJ > PADR) padJ = PADR;

    int prepN = padI > padJ ? padI : padJ;
    prep_kernel<<<(prepN + TPB - 1) / TPB, TPB>>>(beta, gamma, zi, zj, si, sj,
                                                  S_I, S_J, padI, padJ);

    int nDense = gx * gy;               // 2209
    int nTotal = nDense;
    if (nTotal > MAXPART) nTotal = MAXPART;

    fused_kernel<<<nTotal, TPB>>>(beta, gamma, zi, zj, vC, spi, spj,
                                  (float*)d_out, NNZ, gx, nDense, nTotal);
}

// round 16
// speedup vs baseline: 1.3349x; 1.1535x over previous
#include <cuda_runtime.h>
#include <cstdint>

#define EPSC   1e-6f
#define L2E    1.4426950408889634f
#define L2E2C  2.0813689810056077f
#define N2L2E2 -4.1627379620112154f
#define LN2F   0.6931471805599453f
#define TPB    128
#define NWARP  4
#define TILE   128
#define PADR   8192
#define MAXPART 4096

__device__ uint2  gAhi[PADR * 4];
__device__ uint2  gAlo[PADR * 4];
__device__ uint2  gBhi[PADR * 4];
__device__ uint2  gBlo[PADR * 4];
__device__ float2 gNEi[PADR];        // (L2E^2*|a|^2, exp(beta))
__device__ float4 gNEj[PADR / 2];    // (nj'_{2c}, ej_{2c}, nj'_{2c+1}, ej_{2c+1})
__device__ double g_part[MAXPART];
__device__ unsigned int g_count = 0;

__device__ __forceinline__ float ex2_approx(float x) {
    float y; asm("ex2.approx.ftz.f32 %0, %1;" : "=f"(y) : "f"(x)); return y;
}
__device__ __forceinline__ float lg2_approx(float x) {
    float y; asm("lg2.approx.ftz.f32 %0, %1;" : "=f"(y) : "f"(x)); return y;
}
__device__ __forceinline__ float sqrt_approx(float x) {
    float y; asm("sqrt.approx.ftz.f32 %0, %1;" : "=f"(y) : "f"(x)); return y;
}
__device__ __forceinline__ uint32_t to_tf32(float v) {
    uint32_t r; asm("cvt.rna.tf32.f32 %0, %1;" : "=r"(r) : "f"(v)); return r;
}
__device__ __forceinline__ void mma_tf32(float& d0, float& d1, float& d2, float& d3,
                                         uint32_t a0, uint32_t a1, uint32_t a2, uint32_t a3,
                                         uint32_t b0, uint32_t b1) {
    asm volatile(
        "mma.sync.aligned.m16n8k8.row.col.f32.tf32.tf32.f32 "
        "{%0,%1,%2,%3}, {%4,%5,%6,%7}, {%8,%9}, {%0,%1,%2,%3};"
        : "+f"(d0), "+f"(d1), "+f"(d2), "+f"(d3)
        : "r"(a0), "r"(a1), "r"(a2), "r"(a3), "r"(b0), "r"(b1));
}
__device__ __forceinline__ float lgamma1p(float x) {
    float p = 0.035868343f;
    p = fmaf(p, x, -0.193527818f);
    p = fmaf(p, x,  0.482199394f);
    p = fmaf(p, x, -0.756704078f);
    p = fmaf(p, x,  0.918206857f);
    p = fmaf(p, x, -0.897056937f);
    p = fmaf(p, x,  0.988205891f);
    p = fmaf(p, x, -0.577191652f);
    p = fmaf(p, x,  1.0f);
    return lg2_approx(p) * LN2F;
}

// fragment-ordered row store: slot t in [0,4) holds k-dims (t, t+4) as uint2
__device__ __forceinline__ void store8(uint2* hi, uint2* lo, int r, const float* v8) {
    #pragma unroll
    for (int t = 0; t < 4; ++t) {
        uint2 h, l;
        h.x = to_tf32(v8[t]);     l.x = to_tf32(v8[t]     - __uint_as_float(h.x));
        h.y = to_tf32(v8[t + 4]); l.y = to_tf32(v8[t + 4] - __uint_as_float(h.y));
        hi[r * 4 + t] = h;
        lo[r * 4 + t] = l;
    }
}

__global__ void prep_kernel(const float* __restrict__ beta,
                            const float* __restrict__ gamma,
                            const float* __restrict__ zi,
                            const float* __restrict__ zj,
                            const int*   __restrict__ si,
                            const int*   __restrict__ sj,
                            int S_I, int S_J, int padI, int padJ) {
    int r = blockIdx.x * blockDim.x + threadIdx.x;
    if (r < padI) {
        float v[8] = {0.f, 0.f, 0.f, 0.f, 0.f, 0.f, 0.f, 0.f};
        float ni = 0.f, e = 0.f;
        if (r < S_I) {
            int idx = __ldg(si + r);
            float4 a0 = __ldg((const float4*)(zi + (size_t)idx * 8));
            float4 a1 = __ldg((const float4*)(zi + (size_t)idx * 8 + 4));
            float t[8] = {a0.x + EPSC, a0.y + EPSC, a0.z + EPSC, a0.w + EPSC,
                          a1.x + EPSC, a1.y + EPSC, a1.z + EPSC, a1.w + EPSC};
            float n = 0.f;
            #pragma unroll
            for (int k = 0; k < 8; ++k) n = fmaf(t[k], t[k], n);
            #pragma unroll
            for (int k = 0; k < 8; ++k) v[k] = N2L2E2 * t[k];   // -2*L2E^2*(a+eps)
            ni = n * L2E2C;
            e  = ex2_approx(__ldg(beta + idx) * L2E);
        }
        store8(gAhi, gAlo, r, v);
        gNEi[r] = make_float2(ni, e);
    }
    if (r < padJ) {
        float v[8] = {0.f, 0.f, 0.f, 0.f, 0.f, 0.f, 0.f, 0.f};
        float nj = 0.f, e = 0.f;
        if (r < S_J) {
            int idx = __ldg(sj + r);
            float4 b0 = __ldg((const float4*)(zj + (size_t)idx * 8));
            float4 b1 = __ldg((const float4*)(zj + (size_t)idx * 8 + 4));
            v[0]=b0.x; v[1]=b0.y; v[2]=b0.z; v[3]=b0.w;
            v[4]=b1.x; v[5]=b1.y; v[6]=b1.z; v[7]=b1.w;
            float n = 0.f;
            #pragma unroll
            for (int k = 0; k < 8; ++k) n = fmaf(v[k], v[k], n);
            nj = n * L2E2C;
            e  = ex2_approx(__ldg(gamma + idx) * L2E);
        }
        store8(gBhi, gBlo, r, v);
        ((float2*)gNEj)[r] = make_float2(nj, e);
    }
}

__global__ void __launch_bounds__(TPB, 6) fused_kernel(
        const float* __restrict__ beta,  const float* __restrict__ gamma,
        const float* __restrict__ zi,    const float* __restrict__ zj,
        const float* __restrict__ vC,
        const int*   __restrict__ spi,   const int*   __restrict__ spj,
        float* __restrict__ out,
        int nnz, int gx, int nDense, int nTotal) {

    __shared__ double ws[NWARP];
    __shared__ int    s_last;

    const int bid = blockIdx.x;
    const int tid = threadIdx.x;
    const int lane = tid & 31, warp = tid >> 5;

    float dsum = 0.f;
    float lsum = 0.f;

    if (bid < nDense) {
        const int bx = bid % gx, by = bid / gx;
        const int tig = lane & 3, gid = lane >> 2;

        #pragma unroll
        for (int g = 0; g < 2; ++g) {
            const int r0 = bx * TILE + warp * 32 + g * 16 + gid;
            const int r1 = r0 + 8;
            uint2 A0h = __ldg(&gAhi[r0 * 4 + tig]);
            uint2 A1h = __ldg(&gAhi[r1 * 4 + tig]);
            uint2 A0l = __ldg(&gAlo[r0 * 4 + tig]);
            uint2 A1l = __ldg(&gAlo[r1 * 4 + tig]);
            float2 ni0 = __ldg(&gNEi[r0]);
            float2 ni1 = __ldg(&gNEi[r1]);
            float ar0 = 0.f, ar1 = 0.f;
            #pragma unroll 2
            for (int n = 0; n < TILE; n += 8) {
                const int rn = by * TILE + n + gid;
                uint2 Bh = __ldg(&gBhi[rn * 4 + tig]);
                uint2 Bl = __ldg(&gBlo[rn * 4 + tig]);
                float4 ne = __ldg(&gNEj[((by * TILE + n) >> 1) + tig]);
                float hh0=0.f, hh1=0.f, hh2=0.f, hh3=0.f;
                float hl0=0.f, hl1=0.f, hl2=0.f, hl3=0.f;
                float lh0=0.f, lh1=0.f, lh2=0.f, lh3=0.f;
                mma_tf32(hh0,hh1,hh2,hh3, A0h.x,A1h.x,A0h.y,A1h.y, Bh.x,Bh.y);
                mma_tf32(hl0,hl1,hl2,hl3, A0h.x,A1h.x,A0h.y,A1h.y, Bl.x,Bl.y);
                mma_tf32(lh0,lh1,lh2,lh3, A0l.x,A1l.x,A0l.y,A1l.y, Bh.x,Bh.y);
                // per-element base = ni' + nj' (4 row/col combos)
                float b00 = ni0.x + ne.x, b01 = ni0.x + ne.z;
                float b10 = ni1.x + ne.x, b11 = ni1.x + ne.z;
                float x0 = (hh0 + hl0) + (lh0 + b00);
                float x1 = (hh1 + hl1) + (lh1 + b01);
                float x2 = (hh2 + hl2) + (lh2 + b10);
                float x3 = (hh3 + hl3) + (lh3 + b11);
                float e0 = ex2_approx(-sqrt_approx(fmaxf(x0, 0.f)));
                float e1 = ex2_approx(-sqrt_approx(fmaxf(x1, 0.f)));
                float e2 = ex2_approx(-sqrt_approx(fmaxf(x2, 0.f)));
                float e3 = ex2_approx(-sqrt_approx(fmaxf(x3, 0.f)));
                ar0 = fmaf(e0, ne.y, ar0);
                ar0 = fmaf(e1, ne.w, ar0);
                ar1 = fmaf(e2, ne.y, ar1);
                ar1 = fmaf(e3, ne.w, ar1);
            }
            dsum = fmaf(ar0, ni0.y, dsum);
            dsum = fmaf(ar1, ni1.y, dsum);
        }
    }

    // ================= SPARSE link term: all blocks cooperate =================
    {
        int e = bid * TPB + tid;
        int stride = nTotal * TPB;
        #pragma unroll 2
        for (; e < nnz; e += stride) {
            int a = __ldg(spi + e), b = __ldg(spj + e);
            float4 a0 = __ldg((const float4*)(zi + (size_t)a * 8));
            float4 a1 = __ldg((const float4*)(zi + (size_t)a * 8 + 4));
            float4 b0 = __ldg((const float4*)(zj + (size_t)b * 8));
            float4 b1 = __ldg((const float4*)(zj + (size_t)b * 8 + 4));
            float d2 = 0.f, dx;
            dx = a0.x - b0.x + EPSC; d2 = fmaf(dx, dx, d2);
            dx = a0.y - b0.y + EPSC; d2 = fmaf(dx, dx, d2);
            dx = a0.z - b0.z + EPSC; d2 = fmaf(dx, dx, d2);
            dx = a0.w - b0.w + EPSC; d2 = fmaf(dx, dx, d2);
            dx = a1.x - b1.x + EPSC; d2 = fmaf(dx, dx, d2);
            dx = a1.y - b1.y + EPSC; d2 = fmaf(dx, dx, d2);
            dx = a1.z - b1.z + EPSC; d2 = fmaf(dx, dx, d2);
            dx = a1.w - b1.w + EPSC; d2 = fmaf(dx, dx, d2);
            float dist = sqrt_approx(d2);
            float v    = __ldg(vC + e);
            float bias = __ldg(beta + a) + __ldg(gamma + b);
            lsum += fmaf(v, bias - dist, -lgamma1p(v));
        }
    }

    // ---- deterministic block reduction: (link - dense) in double ----
    double t = (double)lsum - (double)dsum;
    #pragma unroll
    for (int o = 16; o; o >>= 1) t += __shfl_down_sync(0xFFFFFFFFu, t, o);
    if (lane == 0) ws[warp] = t;
    __syncthreads();
    if (tid == 0) {
        double b = 0.0;
        #pragma unroll
        for (int k = 0; k < NWARP; ++k) b += ws[k];
        g_part[bid] = b;
        __threadfence();
        unsigned int done = atomicAdd(&g_count, 1u);
        s_last = (done == (unsigned int)(nTotal - 1)) ? 1 : 0;
    }
    __syncthreads();

    if (s_last) {
        __threadfence();
        double s = 0.0;
        for (int k = tid; k < nTotal; k += TPB) s += __ldcg(&g_part[k]);
        #pragma unroll
        for (int o = 16; o; o >>= 1) s += __shfl_down_sync(0xFFFFFFFFu, s, o);
        __syncthreads();
        if (lane == 0) ws[warp] = s;
        __syncthreads();
        if (tid == 0) {
            double r = 0.0;
            #pragma unroll
            for (int k = 0; k < NWARP; ++k) r += ws[k];
            out[0] = (float)r;
            g_count = 0;
        }
    }
}

extern "C" void kernel_launch(void* const* d_in, const int* in_sizes, int n_in,
                              void* d_out, int out_size) {
    const float* beta  = (const float*)d_in[0];
    const float* gamma = (const float*)d_in[1];
    const float* zi    = (const float*)d_in[2];
    const float* zj    = (const float*)d_in[3];
    const float* vC    = (const float*)d_in[4];
    const int*   si    = (const int*)d_in[5];
    const int*   sj    = (const int*)d_in[6];
    const int*   spi   = (const int*)d_in[7];
    const int*   spj   = (const int*)d_in[8];

    int S_I = in_sizes[5];
    int S_J = in_sizes[6];
    int NNZ = in_sizes[4];

    int gx = (S_I + TILE - 1) / TILE;   // 47 for 6000
    int gy = (S_J + TILE - 1) / TILE;   // 47 for 6000
    int padI = gx * TILE;
    int padJ = gy * TILE;
    if (padI > PADR) padI = PADR;
    if (padJ > PADR) padJ = PADR;

    int prepN = padI > padJ ? padI : padJ;
    prep_kernel<<<(prepN + TPB - 1) / TPB, TPB>>>(beta, gamma, zi, zj, si, sj,
                                                  S_I, S_J, padI, padJ);

    int nDense = gx * gy;               // 2209
    int nTotal = nDense;
    if (nTotal > MAXPART) nTotal = MAXPART;

    fused_kernel<<<nTotal, TPB>>>(beta, gamma, zi, zj, vC, spi, spj,
                                  (float*)d_out, NNZ, gx, nDense, nTotal);
}

// round 17
// speedup vs baseline: 1.5857x; 1.1879x over previous
#include <cuda_runtime.h>
#include <cstdint>

#define EPSC   1e-6f
#define L2E    1.4426950408889634f
#define L2E2C  2.0813689810056077f
#define N2L2E2 -4.1627379620112154f
#define LN2F   0.6931471805599453f
#define TPB    128
#define NWARP  4
#define TILE   128
#define PADR   8192
#define MAXPART 4096

__device__ uint2  gAhi[PADR * 4];
__device__ uint2  gAlo[PADR * 4];
__device__ uint2  gBhi[PADR * 4];
__device__ uint2  gBlo[PADR * 4];
__device__ float2 gNEi[PADR];        // (L2E^2*|a|^2, exp(beta))
__device__ float4 gNEj[PADR / 2];    // (nj'_{2c}, ej_{2c}, nj'_{2c+1}, ej_{2c+1})
__device__ double g_part[MAXPART];
__device__ unsigned int g_count = 0;

__device__ __forceinline__ float ex2_approx(float x) {
    float y; asm("ex2.approx.ftz.f32 %0, %1;" : "=f"(y) : "f"(x)); return y;
}
__device__ __forceinline__ float lg2_approx(float x) {
    float y; asm("lg2.approx.ftz.f32 %0, %1;" : "=f"(y) : "f"(x)); return y;
}
__device__ __forceinline__ float sqrt_approx(float x) {
    float y; asm("sqrt.approx.ftz.f32 %0, %1;" : "=f"(y) : "f"(x)); return y;
}
__device__ __forceinline__ uint32_t to_tf32(float v) {
    uint32_t r; asm("cvt.rna.tf32.f32 %0, %1;" : "=r"(r) : "f"(v)); return r;
}
__device__ __forceinline__ void mma_tf32(float& d0, float& d1, float& d2, float& d3,
                                         uint32_t a0, uint32_t a1, uint32_t a2, uint32_t a3,
                                         uint32_t b0, uint32_t b1) {
    asm volatile(
        "mma.sync.aligned.m16n8k8.row.col.f32.tf32.tf32.f32 "
        "{%0,%1,%2,%3}, {%4,%5,%6,%7}, {%8,%9}, {%0,%1,%2,%3};"
        : "+f"(d0), "+f"(d1), "+f"(d2), "+f"(d3)
        : "r"(a0), "r"(a1), "r"(a2), "r"(a3), "r"(b0), "r"(b1));
}
__device__ __forceinline__ float lgamma1p(float x) {
    float p = 0.035868343f;
    p = fmaf(p, x, -0.193527818f);
    p = fmaf(p, x,  0.482199394f);
    p = fmaf(p, x, -0.756704078f);
    p = fmaf(p, x,  0.918206857f);
    p = fmaf(p, x, -0.897056937f);
    p = fmaf(p, x,  0.988205891f);
    p = fmaf(p, x, -0.577191652f);
    p = fmaf(p, x,  1.0f);
    return lg2_approx(p) * LN2F;
}

// fragment-ordered row store: slot t in [0,4) holds k-dims (t, t+4) as uint2
__device__ __forceinline__ void store8(uint2* hi, uint2* lo, int r, const float* v8) {
    #pragma unroll
    for (int t = 0; t < 4; ++t) {
        uint2 h, l;
        h.x = to_tf32(v8[t]);     l.x = to_tf32(v8[t]     - __uint_as_float(h.x));
        h.y = to_tf32(v8[t + 4]); l.y = to_tf32(v8[t + 4] - __uint_as_float(h.y));
        hi[r * 4 + t] = h;
        lo[r * 4 + t] = l;
    }
}

__global__ void prep_kernel(const float* __restrict__ beta,
                            const float* __restrict__ gamma,
                            const float* __restrict__ zi,
                            const float* __restrict__ zj,
                            const int*   __restrict__ si,
                            const int*   __restrict__ sj,
                            int S_I, int S_J, int padI, int padJ) {
    int r = blockIdx.x * blockDim.x + threadIdx.x;
    if (r < padI) {
        float v[8] = {0.f, 0.f, 0.f, 0.f, 0.f, 0.f, 0.f, 0.f};
        float ni = 0.f, e = 0.f;
        if (r < S_I) {
            int idx = __ldg(si + r);
            float4 a0 = __ldg((const float4*)(zi + (size_t)idx * 8));
            float4 a1 = __ldg((const float4*)(zi + (size_t)idx * 8 + 4));
            float t[8] = {a0.x + EPSC, a0.y + EPSC, a0.z + EPSC, a0.w + EPSC,
                          a1.x + EPSC, a1.y + EPSC, a1.z + EPSC, a1.w + EPSC};
            float n = 0.f;
            #pragma unroll
            for (int k = 0; k < 8; ++k) n = fmaf(t[k], t[k], n);
            #pragma unroll
            for (int k = 0; k < 8; ++k) v[k] = N2L2E2 * t[k];   // -2*L2E^2*(a+eps)
            ni = n * L2E2C;
            e  = ex2_approx(__ldg(beta + idx) * L2E);
        }
        store8(gAhi, gAlo, r, v);
        gNEi[r] = make_float2(ni, e);
    }
    if (r < padJ) {
        float v[8] = {0.f, 0.f, 0.f, 0.f, 0.f, 0.f, 0.f, 0.f};
        float nj = 0.f, e = 0.f;
        if (r < S_J) {
            int idx = __ldg(sj + r);
            float4 b0 = __ldg((const float4*)(zj + (size_t)idx * 8));
            float4 b1 = __ldg((const float4*)(zj + (size_t)idx * 8 + 4));
            v[0]=b0.x; v[1]=b0.y; v[2]=b0.z; v[3]=b0.w;
            v[4]=b1.x; v[5]=b1.y; v[6]=b1.z; v[7]=b1.w;
            float n = 0.f;
            #pragma unroll
            for (int k = 0; k < 8; ++k) n = fmaf(v[k], v[k], n);
            nj = n * L2E2C;
            e  = ex2_approx(__ldg(gamma + idx) * L2E);
        }
        store8(gBhi, gBlo, r, v);
        ((float2*)gNEj)[r] = make_float2(nj, e);
    }
}

__global__ void __launch_bounds__(TPB, 6) fused_kernel(
        const float* __restrict__ beta,  const float* __restrict__ gamma,
        const float* __restrict__ zi,    const float* __restrict__ zj,
        const float* __restrict__ vC,
        const int*   __restrict__ spi,   const int*   __restrict__ spj,
        float* __restrict__ out,
        int nnz, int gx, int nDense, int nTotal) {

    __shared__ uint2  sBh[TILE * 4];     // 4KB
    __shared__ uint2  sBl[TILE * 4];     // 4KB
    __shared__ float4 sNE[TILE / 2];     // 1KB
    __shared__ double ws[NWARP];
    __shared__ int    s_last;

    const int bid = blockIdx.x;
    const int tid = threadIdx.x;
    const int lane = tid & 31, warp = tid >> 5;

    float dsum = 0.f;
    float lsum = 0.f;

    if (bid < nDense) {
        const int bx = bid % gx, by = bid / gx;
        const int tig = lane & 3, gid = lane >> 2;

        // ---- stage B tile + NEj into smem (straight memcpy, prep-formatted) ----
        {
            const uint4* srcH = (const uint4*)&gBhi[by * TILE * 4];  // 256 uint4
            const uint4* srcL = (const uint4*)&gBlo[by * TILE * 4];
            uint4* dstH = (uint4*)sBh;
            uint4* dstL = (uint4*)sBl;
            #pragma unroll
            for (int i = 0; i < 2; ++i) {
                dstH[tid + i * TPB] = __ldg(&srcH[tid + i * TPB]);
                dstL[tid + i * TPB] = __ldg(&srcL[tid + i * TPB]);
            }
            if (tid < TILE / 2) sNE[tid] = __ldg(&gNEj[by * (TILE / 2) + tid]);
        }
        __syncthreads();

        #pragma unroll
        for (int g = 0; g < 2; ++g) {
            const int r0 = bx * TILE + warp * 32 + g * 16 + gid;
            const int r1 = r0 + 8;
            uint2 A0h = __ldg(&gAhi[r0 * 4 + tig]);
            uint2 A1h = __ldg(&gAhi[r1 * 4 + tig]);
            uint2 A0l = __ldg(&gAlo[r0 * 4 + tig]);
            uint2 A1l = __ldg(&gAlo[r1 * 4 + tig]);
            float2 ni0 = __ldg(&gNEi[r0]);
            float2 ni1 = __ldg(&gNEi[r1]);
            float ar0 = 0.f, ar1 = 0.f;
            #pragma unroll 2
            for (int n = 0; n < TILE; n += 8) {
                uint2 Bh = sBh[(n + gid) * 4 + tig];
                uint2 Bl = sBl[(n + gid) * 4 + tig];
                float4 ne = sNE[(n >> 1) + tig];
                // base folded into hh accumulator init (MMA C-operand)
                float hh0 = ni0.x + ne.x, hh1 = ni0.x + ne.z;
                float hh2 = ni1.x + ne.x, hh3 = ni1.x + ne.z;
                float hl0=0.f, hl1=0.f, hl2=0.f, hl3=0.f;
                float lh0=0.f, lh1=0.f, lh2=0.f, lh3=0.f;
                mma_tf32(hh0,hh1,hh2,hh3, A0h.x,A1h.x,A0h.y,A1h.y, Bh.x,Bh.y);
                mma_tf32(hl0,hl1,hl2,hl3, A0h.x,A1h.x,A0h.y,A1h.y, Bl.x,Bl.y);
                mma_tf32(lh0,lh1,lh2,lh3, A0l.x,A1l.x,A0l.y,A1l.y, Bh.x,Bh.y);
                float x0 = (hh0 + hl0) + lh0;
                float x1 = (hh1 + hl1) + lh1;
                float x2 = (hh2 + hl2) + lh2;
                float x3 = (hh3 + hl3) + lh3;
                float e0 = ex2_approx(-sqrt_approx(fmaxf(x0, 0.f)));
                float e1 = ex2_approx(-sqrt_approx(fmaxf(x1, 0.f)));
                float e2 = ex2_approx(-sqrt_approx(fmaxf(x2, 0.f)));
                float e3 = ex2_approx(-sqrt_approx(fmaxf(x3, 0.f)));
                ar0 = fmaf(e0, ne.y, ar0);
                ar0 = fmaf(e1, ne.w, ar0);
                ar1 = fmaf(e2, ne.y, ar1);
                ar1 = fmaf(e3, ne.w, ar1);
            }
            dsum = fmaf(ar0, ni0.y, dsum);
            dsum = fmaf(ar1, ni1.y, dsum);
        }
    }

    // ================= SPARSE link term: all blocks cooperate =================
    {
        int e = bid * TPB + tid;
        int stride = nTotal * TPB;
        #pragma unroll 2
        for (; e < nnz; e += stride) {
            int a = __ldg(spi + e), b = __ldg(spj + e);
            float4 a0 = __ldg((const float4*)(zi + (size_t)a * 8));
            float4 a1 = __ldg((const float4*)(zi + (size_t)a * 8 + 4));
            float4 b0 = __ldg((const float4*)(zj + (size_t)b * 8));
            float4 b1 = __ldg((const float4*)(zj + (size_t)b * 8 + 4));
            float d2 = 0.f, dx;
            dx = a0.x - b0.x + EPSC; d2 = fmaf(dx, dx, d2);
            dx = a0.y - b0.y + EPSC; d2 = fmaf(dx, dx, d2);
            dx = a0.z - b0.z + EPSC; d2 = fmaf(dx, dx, d2);
            dx = a0.w - b0.w + EPSC; d2 = fmaf(dx, dx, d2);
            dx = a1.x - b1.x + EPSC; d2 = fmaf(dx, dx, d2);
            dx = a1.y - b1.y + EPSC; d2 = fmaf(dx, dx, d2);
            dx = a1.z - b1.z + EPSC; d2 = fmaf(dx, dx, d2);
            dx = a1.w - b1.w + EPSC; d2 = fmaf(dx, dx, d2);
            float dist = sqrt_approx(d2);
            float v    = __ldg(vC + e);
            float bias = __ldg(beta + a) + __ldg(gamma + b);
            lsum += fmaf(v, bias - dist, -lgamma1p(v));
        }
    }

    // ---- deterministic block reduction: (link - dense) in double ----
    double t = (double)lsum - (double)dsum;
    #pragma unroll
    for (int o = 16; o; o >>= 1) t += __shfl_down_sync(0xFFFFFFFFu, t, o);
    if (lane == 0) ws[warp] = t;
    __syncthreads();
    if (tid == 0) {
        double b = 0.0;
        #pragma unroll
        for (int k = 0; k < NWARP; ++k) b += ws[k];
        g_part[bid] = b;
        __threadfence();
        unsigned int done = atomicAdd(&g_count, 1u);
        s_last = (done == (unsigned int)(nTotal - 1)) ? 1 : 0;
    }
    __syncthreads();

    if (s_last) {
        __threadfence();
        double s = 0.0;
        for (int k = tid; k < nTotal; k += TPB) s += __ldcg(&g_part[k]);
        #pragma unroll
        for (int o = 16; o; o >>= 1) s += __shfl_down_sync(0xFFFFFFFFu, s, o);
        __syncthreads();
        if (lane == 0) ws[warp] = s;
        __syncthreads();
        if (tid == 0) {
            double r = 0.0;
            #pragma unroll
            for (int k = 0; k < NWARP; ++k) r += ws[k];
            out[0] = (float)r;
            g_count = 0;
        }
    }
}

extern "C" void kernel_launch(void* const* d_in, const int* in_sizes, int n_in,
                              void* d_out, int out_size) {
    const float* beta  = (const float*)d_in[0];
    const float* gamma = (const float*)d_in[1];
    const float* zi    = (const float*)d_in[2];
    const float* zj    = (const float*)d_in[3];
    const float* vC    = (const float*)d_in[4];
    const int*   si    = (const int*)d_in[5];
    const int*   sj    = (const int*)d_in[6];
    const int*   spi   = (const int*)d_in[7];
    const int*   spj   = (const int*)d_in[8];

    int S_I = in_sizes[5];
    int S_J = in_sizes[6];
    int NNZ = in_sizes[4];

    int gx = (S_I + TILE - 1) / TILE;   // 47 for 6000
    int gy = (S_J + TILE - 1) / TILE;   // 47 for 6000
    int padI = gx * TILE;
    int padJ = gy * TILE;
    if (padI > PADR) padI = PADR;
    if (padJ > PADR) padJ = PADR;

    int prepN = padI > padJ ? padI : padJ;
    prep_kernel<<<(prepN + TPB - 1) / TPB, TPB>>>(beta, gamma, zi, zj, si, sj,
                                                  S_I, S_J, padI, padJ);

    int nDense = gx * gy;               // 2209
    int nTotal = nDense;
    if (nTotal > MAXPART) nTotal = MAXPART;

    fused_kernel<<<nTotal, TPB>>>(beta, gamma, zi, zj, vC, spi, spj,
                                  (float*)d_out, NNZ, gx, nDense, nTotal);
}